// round 6
// baseline (speedup 1.0000x reference)
#include <cuda_runtime.h>

// Single-node pitch loss, block-aggregated combine.
//
// One warp per note (grid 128 x 256). Each lane loads one frame per track
// (coalesced 128B/warp/track), the warp reduces the gen-t DIFFERENCE
// (5 shuffles), leader tests |sum| > 0.5*len (no division).
//
// Per-block: __syncthreads_count collapses the 8 warp hits into one count.
// Cross-block: ONE packed 64-bit atomicAdd per block into g_acc =
// (hits << 32) | blocks_done. The block whose returned low word equals
// gridDim.x-1 is the last arriver; the final hit total is already in the
// return value, so it writes the loss and swaps g_acc back to 0 (all adds
// are serialized before it -> race-free, deterministic across graph
// replays; integer accumulation is order-independent -> bit-exact).
__device__ unsigned long long g_acc = 0ull;

__global__ void __launch_bounds__(256, 1)
pitch_loss_kernel(const float* __restrict__ gen_f0,
                  const float* __restrict__ t_f0,
                  const int*   __restrict__ onset,
                  const int*   __restrict__ offset,
                  float*       __restrict__ out,
                  int N) {
    const int gwarp = (blockIdx.x * blockDim.x + threadIdx.x) >> 5;
    const int lane  = threadIdx.x & 31;

    int hit = 0;
    if (gwarp < N) {
        const int a = onset[gwarp];
        const int b = offset[gwarp];

        float d = 0.0f;
        for (int i = a + lane; i < b; i += 32)
            d += gen_f0[i] - t_f0[i];

        #pragma unroll
        for (int o = 16; o > 0; o >>= 1)
            d += __shfl_down_sync(0xFFFFFFFFu, d, o);

        if (lane == 0)
            hit = (fabsf(d) > 0.5f * (float)(b - a)) ? 1 : 0;
    }

    // Collapse the block's warp-leader hits into one count (also acts as the
    // block-wide barrier; every thread participates, no early returns above).
    const int blk_hits = __syncthreads_count(hit);

    if (threadIdx.x == 0) {
        const unsigned long long contrib =
            ((unsigned long long)(unsigned)blk_hits << 32) | 1ull;
        const unsigned long long old = atomicAdd(&g_acc, contrib);

        if ((unsigned)(old & 0xFFFFFFFFull) == gridDim.x - 1u) {
            const unsigned total = (unsigned)(old >> 32) + (unsigned)blk_hits;
            out[0] = (float)total / (float)N;
            atomicExch(&g_acc, 0ull);   // reset for the next graph replay
        }
    }
}

extern "C" void kernel_launch(void* const* d_in, const int* in_sizes, int n_in,
                              void* d_out, int out_size) {
    const float* gen_f0 = (const float*)d_in[0];
    const float* t_f0   = (const float*)d_in[1];
    const int*   onset  = (const int*)d_in[2];
    const int*   offset = (const int*)d_in[3];
    float* out = (float*)d_out;

    const int N = in_sizes[2];   // number of notes (1024)

    const int THREADS = 256;                              // 8 warps per block
    const int blocks  = (N * 32 + THREADS - 1) / THREADS; // 128
    pitch_loss_kernel<<<blocks, THREADS>>>(gen_f0, t_f0, onset, offset, out, N);
}

// round 7
// speedup vs baseline: 1.0481x; 1.0481x over previous
#include <cuda_runtime.h>

// Pitch loss, one kernel node, 4 notes per warp via vectorized loads.
//
// Notes are contiguous segments, so a warp assigned notes 4w..4w+3 covers a
// contiguous 512B span per track: each lane issues ONE LDG.128 per track
// (lane>>3 selects the note, lane&7 the float4 within it). A width-8 shuffle
// reduce (3 shuffles) yields the per-note gen-t difference sum; the group
// leader tests |sum| > 0.5*len (no division). __syncthreads_count collapses
// the block's hits; one packed 64-bit atomicAdd per block combines across
// blocks: g_acc = (hits << 32) | blocks_done. The block whose returned low
// word equals gridDim.x-1 already holds the final total in the return value,
// writes the loss, and swaps g_acc back to 0 (all adds serialize before it ->
// race-free, bit-exact, deterministic across graph replays).
__device__ unsigned long long g_acc = 0ull;

__global__ void __launch_bounds__(256, 1)
pitch_loss_kernel(const float* __restrict__ gen_f0,
                  const float* __restrict__ t_f0,
                  const int*   __restrict__ onset,
                  const int*   __restrict__ offset,
                  float*       __restrict__ out,
                  int N) {
    const int lane  = threadIdx.x & 31;
    const int sub   = lane & 7;                        // float4 slot in note
    const int grp   = lane >> 3;                       // which of 4 notes
    const int gwarp = (blockIdx.x * blockDim.x + threadIdx.x) >> 5;
    const int note  = gwarp * 4 + grp;

    int hit = 0;
    if (note < N) {
        const int a   = onset[note];
        const int b   = offset[note];
        const int len = b - a;

        float d;
        if (len == 32 && (a & 3) == 0) {
            // Fast path: one float4 per lane per track covers the segment.
            const float4 g = ((const float4*)(gen_f0 + a))[sub];
            const float4 t = ((const float4*)(t_f0  + a))[sub];
            d = ((g.x - t.x) + (g.y - t.y)) + ((g.z - t.z) + (g.w - t.w));
        } else {
            // General path: strided scalar loads over the segment.
            d = 0.0f;
            for (int i = a + sub; i < b; i += 8)
                d += gen_f0[i] - t_f0[i];
        }

        // Reduce within the 8-lane group (width = 8).
        #pragma unroll
        for (int o = 4; o > 0; o >>= 1)
            d += __shfl_down_sync(0xFFFFFFFFu, d, o, 8);

        if (sub == 0)
            hit = (fabsf(d) > 0.5f * (float)len) ? 1 : 0;
    }

    // Per-block hit count; also the block-wide barrier (no early returns).
    const int blk_hits = __syncthreads_count(hit);

    if (threadIdx.x == 0) {
        const unsigned long long contrib =
            ((unsigned long long)(unsigned)blk_hits << 32) | 1ull;
        const unsigned long long old = atomicAdd(&g_acc, contrib);

        if ((unsigned)(old & 0xFFFFFFFFull) == gridDim.x - 1u) {
            const unsigned total = (unsigned)(old >> 32) + (unsigned)blk_hits;
            out[0] = (float)total / (float)N;
            atomicExch(&g_acc, 0ull);   // reset for the next graph replay
        }
    }
}

extern "C" void kernel_launch(void* const* d_in, const int* in_sizes, int n_in,
                              void* d_out, int out_size) {
    const float* gen_f0 = (const float*)d_in[0];
    const float* t_f0   = (const float*)d_in[1];
    const int*   onset  = (const int*)d_in[2];
    const int*   offset = (const int*)d_in[3];
    float* out = (float*)d_out;

    const int N = in_sizes[2];   // number of notes (1024)

    const int THREADS = 256;                         // 8 warps = 32 notes/block
    const int warps   = (N + 3) / 4;                 // 4 notes per warp
    const int blocks  = (warps * 32 + THREADS - 1) / THREADS;   // 32
    pitch_loss_kernel<<<blocks, THREADS>>>(gen_f0, t_f0, onset, offset, out, N);
}

// round 8
// speedup vs baseline: 1.1237x; 1.0722x over previous
#include <cuda_runtime.h>

// Pitch loss: memset node for zero-init + one minimal kernel.
//
// Grid 32 x 256 = 256 warps = 1024 eight-lane groups, one note each. Notes
// are contiguous 32-frame segments, so each lane issues ONE LDG.128 per track
// (warp covers 512B contiguous per track -> fully coalesced). Three width-8
// shuffles reduce the gen-t difference; the group leader tests
// |sum| > 0.5*len (no division) and, only on a hit, issues a fire-and-forget
// float atomicAdd(out, 1/N). The unused return compiles to REDG (no-return
// reduction): no 318-cycle round trip, no completion tail, warps retire
// immediately. No __syncthreads, no device scratch, no second kernel node.
//
// Determinism: every contribution is exactly 2^-10 and all partial sums
// m/1024 (m <= 1024) are exactly representable in fp32, so the accumulation
// is order-independent and bit-exact across graph replays. d_out is zeroed
// by a memset node in the same stream (ordered before the kernel).
__global__ void __launch_bounds__(256, 1)
pitch_loss_kernel(const float* __restrict__ gen_f0,
                  const float* __restrict__ t_f0,
                  const int*   __restrict__ onset,
                  const int*   __restrict__ offset,
                  float*       __restrict__ out,
                  int N) {
    const int lane  = threadIdx.x & 31;
    const int sub   = lane & 7;                       // float4 slot in note
    const int grp   = lane >> 3;                      // which of warp's 4 notes
    const int gwarp = (blockIdx.x * blockDim.x + threadIdx.x) >> 5;
    const int note  = gwarp * 4 + grp;

    if (note >= N) return;

    const int a   = onset[note];
    const int b   = offset[note];
    const int len = b - a;

    float d;
    if (len == 32 && (a & 3) == 0) {
        // Fast path: one float4 per lane per track covers the segment.
        const float4 g = ((const float4*)(gen_f0 + a))[sub];
        const float4 t = ((const float4*)(t_f0  + a))[sub];
        d = ((g.x - t.x) + (g.y - t.y)) + ((g.z - t.z) + (g.w - t.w));
    } else {
        // General path: strided scalar loads over the segment.
        d = 0.0f;
        for (int i = a + sub; i < b; i += 8)
            d += gen_f0[i] - t_f0[i];
    }

    // Reduce within the 8-lane group (width = 8).
    #pragma unroll
    for (int o = 4; o > 0; o >>= 1)
        d += __shfl_down_sync(0xFFFFFFFFu, d, o, 8);

    // Group leader: predicated fire-and-forget reduction into the output.
    if (sub == 0 && fabsf(d) > 0.5f * (float)len)
        atomicAdd(out, 1.0f / (float)N);   // return unused -> REDG
}

extern "C" void kernel_launch(void* const* d_in, const int* in_sizes, int n_in,
                              void* d_out, int out_size) {
    const float* gen_f0 = (const float*)d_in[0];
    const float* t_f0   = (const float*)d_in[1];
    const int*   onset  = (const int*)d_in[2];
    const int*   offset = (const int*)d_in[3];
    float* out = (float*)d_out;

    const int N = in_sizes[2];   // number of notes (1024)

    // Zero the scalar output with a memset node (graph-capturable, async,
    // same stream -> ordered before the kernel's atomics).
    cudaMemsetAsync(out, 0, sizeof(float));

    const int THREADS = 256;                                  // 8 warps/block
    const int warps   = (N + 3) / 4;                          // 4 notes/warp
    const int blocks  = (warps * 32 + THREADS - 1) / THREADS; // 32
    pitch_loss_kernel<<<blocks, THREADS>>>(gen_f0, t_f0, onset, offset, out, N);
}